// round 16
// baseline (speedup 1.0000x reference)
#include <cuda_runtime.h>
#include <cuda_fp16.h>

#define INV_TAU (1.0f/512.0f)

// Scratch (no cudaMalloc allowed)
__device__ __half g_Xt[8ul*1024*1024];     // x^T fp16 [b][l][s]
__device__ __half g_Yt[8ul*1024*1024];     // y^T fp16 [b][l][s]
__device__ __half g_Ot[8ul*1024*1024];     // O^T fp16 [b][m][s]
__device__ __half g_X16[8ul*1024*1024];    // x fp16 [b][s][l]
__device__ __half g_Xd[8ul*1024*1024];     // x/Z fp16 [b][s][l]
__device__ __half g_Wh[3ul*1024*1024];     // Wk,Wq,Wp fp16 row-major
__device__ __half g_Kt[128ul*1024*64];     // K^T fp16 [bh][l][d]
__device__ __half g_Qt[128ul*1024*64];     // Q^T fp16 [bh][m][d]
__device__ float  g_Z[128ul*1024];

__device__ __forceinline__ unsigned f2h2(float a, float b) {
  __half2 h = __floats2half2_rn(a, b);
  return *(unsigned*)&h;
}
__device__ __forceinline__ unsigned su32(const void* p) {
  unsigned a;
  asm("{ .reg .u64 t; cvta.to.shared.u64 t, %1; cvt.u32.u64 %0, t; }"
      : "=r"(a) : "l"(p));
  return a;
}
__device__ __forceinline__ void mma16(float* c, unsigned a0, unsigned a1,
                                      unsigned a2, unsigned a3,
                                      unsigned b0, unsigned b1) {
  asm("mma.sync.aligned.m16n8k16.row.col.f32.f16.f16.f32 "
      "{%0,%1,%2,%3}, {%4,%5,%6,%7}, {%8,%9}, {%0,%1,%2,%3};"
      : "+f"(c[0]), "+f"(c[1]), "+f"(c[2]), "+f"(c[3])
      : "r"(a0), "r"(a1), "r"(a2), "r"(a3), "r"(b0), "r"(b1));
}
#define LDSM4(r0, r1, r2, r3, addr) \
  asm volatile("ldmatrix.sync.aligned.m8n8.x4.shared.b16 {%0,%1,%2,%3}, [%4];" \
               : "=r"(r0), "=r"(r1), "=r"(r2), "=r"(r3) : "r"(addr))
__device__ __forceinline__ void cpa16(unsigned dst, const void* src) {
  asm volatile("cp.async.ca.shared.global [%0], [%1], 16;"
               :: "r"(dst), "l"(src));
}
#define CP_COMMIT() asm volatile("cp.async.commit_group;")
#define CP_WAIT1()  asm volatile("cp.async.wait_group 1;")
#define CP_WAIT0()  asm volatile("cp.async.wait_group 0;")

// ---------------------------------------------------------------------------
// cvtW: convert the 3 weight matrices fp32->fp16 in one launch (grid 3072)
// ---------------------------------------------------------------------------
__global__ __launch_bounds__(256) void cvtW(
    const float* __restrict__ w0, const float* __restrict__ w1,
    const float* __restrict__ w2, __half* __restrict__ out) {
  int blk = blockIdx.x;
  int which = blk >> 10;
  const float* src = (which == 0) ? w0 : (which == 1) ? w1 : w2;
  size_t off = ((size_t)(blk & 1023)*256 + threadIdx.x)*4;
  float4 v = *(const float4*)&src[off];
  *(uint2*)&out[(size_t)which*1048576 + off] =
      make_uint2(f2h2(v.x, v.y), f2h2(v.z, v.w));
}

// ---------------------------------------------------------------------------
// prep_xt: read fp32 in once; write fp16 transposed (Tt) and, if St != null,
// fp16 straight copy (same layout as input).
// ---------------------------------------------------------------------------
__global__ __launch_bounds__(256, 2) void prep_xt(
    const float* __restrict__ in, __half* __restrict__ Tt,
    __half* __restrict__ St) {
  __shared__ float t[64][65];
  const int z = blockIdx.z;
  const int r0 = blockIdx.y * 64, c0 = blockIdx.x * 64;
  const int tid = threadIdx.x;
  const size_t base = (size_t)z * 1024 * 1024;
  const int tr = tid >> 4, tc4 = (tid & 15) * 4;
#pragma unroll
  for (int i = 0; i < 4; i++) {
    int row = tr + i * 16;
    float4 v = *(const float4*)&in[base + (size_t)(r0 + row) * 1024 + c0 + tc4];
    t[row][tc4+0] = v.x; t[row][tc4+1] = v.y;
    t[row][tc4+2] = v.z; t[row][tc4+3] = v.w;
    if (St)
      *(uint2*)&St[base + (size_t)(r0 + row) * 1024 + c0 + tc4] =
          make_uint2(f2h2(v.x, v.y), f2h2(v.z, v.w));
  }
  __syncthreads();
#pragma unroll
  for (int i = 0; i < 4; i++) {
    int orow = tr + i * 16;
    uint2 u;
    u.x = f2h2(t[tc4+0][orow], t[tc4+1][orow]);
    u.y = f2h2(t[tc4+2][orow], t[tc4+3][orow]);
    *(uint2*)&Tt[base + (size_t)(c0 + orow) * 1024 + r0 + tc4] = u;
  }
}

// ---------------------------------------------------------------------------
// proj: C = W fp16 @ X + bias.  k-step 64, 3-stage cp.async ring, 1 sync/iter.
// mode 0 (grid z=16): which = z>>3 picks set; fp16 transposed per-head out.
// mode 1 (grid z=8): set 0, fp32 out.
// smem halves: A_i @ i*9216 (i=0..2), B_i @ 27648 + i*9216.  Total 55296.
// ---------------------------------------------------------------------------
__global__ __launch_bounds__(256, 2) void proj_h(
    const __half* __restrict__ W0, const __half* __restrict__ W1,
    const __half* __restrict__ X0, const __half* __restrict__ X1,
    const float* __restrict__ b0f, const float* __restrict__ b1f,
    __half* __restrict__ T0, __half* __restrict__ T1,
    float* __restrict__ Cout, int mode) {
  extern __shared__ __half psm[];
  const int z = blockIdx.z;
  const int which = (mode == 0) ? (z >> 3) : 0;
  const int b = z & 7;
  const __half* Wsel = which ? W1 : W0;
  const __half* Xsel = (which ? X1 : X0) + (size_t)b*1024*1024;
  const float* bias = which ? b1f : b0f;
  const int row0 = blockIdx.y*128, col0 = blockIdx.x*128;
  const int tid = threadIdx.x, wid = tid>>5, lane = tid&31;
  const int gi = lane>>2, tj = lane&3;
  const int wm = (wid>>2)*64, wn = (wid&3)*32;
  const unsigned smA = su32(psm);
  const int laneA = (((lane&7) + ((lane>>3)&1)*8)*72 + ((lane>>4)&1)*8)*2;
  const int laneB = (((lane&7) + ((lane>>4)&1)*8)*72 + ((lane>>3)&1)*8)*2;

  float acc[4][4][4] = {};

  auto issue = [&](int buf, int k0) {
#pragma unroll
    for (int i = 0; i < 4; i++) {
      int id = tid*4 + i;                 // 0..1023
      int row = id>>3, c8 = (id&7)*8;
      cpa16(smA + (buf*9216 + row*72 + c8)*2,
            &Wsel[(size_t)(row0 + row)*1024 + k0 + c8]);
      cpa16(smA + (27648 + buf*9216 + row*72 + c8)*2,
            &Xsel[(size_t)(col0 + row)*1024 + k0 + c8]);
    }
    CP_COMMIT();
  };
  issue(0, 0);
  issue(1, 64);

  for (int s = 0; s < 16; s++) {
    const int cur = s % 3;
    if (s < 15) CP_WAIT1(); else CP_WAIT0();
    __syncthreads();
#pragma unroll
    for (int c = 0; c < 4; c++) {
      unsigned a[4][4], bb[4][2];
#pragma unroll
      for (int mt = 0; mt < 4; mt++)
        LDSM4(a[mt][0], a[mt][1], a[mt][2], a[mt][3],
              smA + (cur*9216 + (wm + mt*16)*72 + c*16)*2 + laneA);
      LDSM4(bb[0][0], bb[0][1], bb[1][0], bb[1][1],
            smA + (27648 + cur*9216 + wn*72 + c*16)*2 + laneB);
      LDSM4(bb[2][0], bb[2][1], bb[3][0], bb[3][1],
            smA + (27648 + cur*9216 + (wn + 16)*72 + c*16)*2 + laneB);
#pragma unroll
      for (int mt = 0; mt < 4; mt++)
#pragma unroll
        for (int nt = 0; nt < 4; nt++)
          mma16(acc[mt][nt], a[mt][0],a[mt][1],a[mt][2],a[mt][3],
                bb[nt][0], bb[nt][1]);
    }
    if (s < 14) issue((s + 2) % 3, (s + 2)*64);
  }

  if (mode == 1) {
    float* Cb = Cout + (size_t)b*1024*1024;
#pragma unroll
    for (int mt = 0; mt < 4; mt++) {
      int r0_ = row0 + wm + mt*16 + gi;
      float bv0 = bias[r0_], bv1 = bias[r0_+8];
#pragma unroll
      for (int nt = 0; nt < 4; nt++) {
        int cc = col0 + wn + nt*8 + 2*tj;
        *(float2*)&Cb[(size_t)r0_*1024 + cc] =
            make_float2(acc[mt][nt][0]+bv0, acc[mt][nt][1]+bv0);
        *(float2*)&Cb[(size_t)(r0_+8)*1024 + cc] =
            make_float2(acc[mt][nt][2]+bv1, acc[mt][nt][3]+bv1);
      }
    }
  } else {
    __half* Tout = which ? T1 : T0;
    __half* Cts = psm;   // 128*136 halves
    __syncthreads();     // all warps done reading the A/B rings
#pragma unroll
    for (int mt = 0; mt < 4; mt++) {
      int r_ = wm + mt*16 + gi;
      float bv0 = bias[row0 + r_], bv1 = bias[row0 + r_ + 8];
#pragma unroll
      for (int nt = 0; nt < 4; nt++) {
        int c_ = wn + nt*8 + 2*tj;
        Cts[c_*136 + r_]       = __float2half(acc[mt][nt][0] + bv0);
        Cts[(c_+1)*136 + r_]   = __float2half(acc[mt][nt][1] + bv0);
        Cts[c_*136 + r_+8]     = __float2half(acc[mt][nt][2] + bv1);
        Cts[(c_+1)*136 + r_+8] = __float2half(acc[mt][nt][3] + bv1);
      }
    }
    __syncthreads();
    int l = tid>>1, part = tid&1;
    size_t obase = ((size_t)(b*16 + (row0>>6) + part)*1024 + col0 + l)*64;
#pragma unroll
    for (int j = 0; j < 8; j++)
      *(uint4*)&Tout[obase + j*8] = *(const uint4*)&Cts[l*136 + part*64 + j*8];
  }
}

// ---------------------------------------------------------------------------
// zpass: Z[l] = sum_m exp(S[l,m]/tau), S^T = Q^T K.  Epilogue also writes
// Xd = x/Z for this (bh, l-tile) — fused former xdiv kernel.
// ---------------------------------------------------------------------------
__global__ __launch_bounds__(256, 2) void zpass_h(
    const __half* __restrict__ Kt, const __half* __restrict__ Qt,
    const __half* __restrict__ X16, float* __restrict__ Z,
    __half* __restrict__ Xd) {
  extern __shared__ __half zsm[];
  __half* Ks = zsm;
  __half* Qs = zsm + 9216;
  float* Zp = (float*)(zsm + 27648);
  const int bh = blockIdx.y, l0 = blockIdx.x*128;
  const int b = bh>>4, h = bh&15;
  const __half* Kb = Kt + (size_t)bh*65536;
  const __half* Qb = Qt + (size_t)bh*65536;
  const int tid = threadIdx.x, wid = tid>>5, lane = tid&31;
  const int gi = lane>>2, tj = lane&3;
  const int wm_ = (wid>>2)*64, wl_ = (wid&3)*32;
  const int r = tid>>1, sg = (tid&1)*32;
  const unsigned smK = su32(Ks), smQ = su32(Qs);
  const int laneA = (((lane&7) + ((lane>>3)&1)*8)*72 + ((lane>>4)&1)*8)*2;
  const int laneB = (((lane&7) + ((lane>>4)&1)*8)*72 + ((lane>>3)&1)*8)*2;

  {
    const uint4* s = (const uint4*)&Kb[(size_t)(l0 + r)*64 + sg];
    uint4* d = (uint4*)&Ks[r*72 + sg];
    d[0]=s[0]; d[1]=s[1]; d[2]=s[2]; d[3]=s[3];
  }
  uint4 pq[4];
  {
    const uint4* s = (const uint4*)&Qb[(size_t)r*64 + sg];
    pq[0]=s[0]; pq[1]=s[1]; pq[2]=s[2]; pq[3]=s[3];
    uint4* d = (uint4*)&Qs[r*72 + sg];
    d[0]=pq[0]; d[1]=pq[1]; d[2]=pq[2]; d[3]=pq[3];
  }
  __syncthreads();

  float rs[4][2] = {};
  for (int m0 = 0; m0 < 1024; m0 += 128) {
    const int cur = (m0 >> 7) & 1, nxt = cur ^ 1;
    if (m0 < 896) {
      const uint4* s = (const uint4*)&Qb[(size_t)(m0 + 128 + r)*64 + sg];
      pq[0]=s[0]; pq[1]=s[1]; pq[2]=s[2]; pq[3]=s[3];
    }
    float S[4][4][4] = {};
#pragma unroll
    for (int c = 0; c < 4; c++) {
      unsigned a[4][4], bb[4][2];
#pragma unroll
      for (int mt = 0; mt < 4; mt++)
        LDSM4(a[mt][0], a[mt][1], a[mt][2], a[mt][3],
              smQ + cur*18432 + ((wm_ + mt*16)*72 + c*16)*2 + laneA);
      LDSM4(bb[0][0], bb[0][1], bb[1][0], bb[1][1],
            smK + (wl_*72 + c*16)*2 + laneB);
      LDSM4(bb[2][0], bb[2][1], bb[3][0], bb[3][1],
            smK + ((wl_ + 16)*72 + c*16)*2 + laneB);
#pragma unroll
      for (int mt = 0; mt < 4; mt++)
#pragma unroll
        for (int nt = 0; nt < 4; nt++)
          mma16(S[mt][nt], a[mt][0],a[mt][1],a[mt][2],a[mt][3],
                bb[nt][0], bb[nt][1]);
    }
#pragma unroll
    for (int mt = 0; mt < 4; mt++)
#pragma unroll
      for (int nt = 0; nt < 4; nt++) {
        rs[nt][0] += __expf(S[mt][nt][0]*INV_TAU) + __expf(S[mt][nt][2]*INV_TAU);
        rs[nt][1] += __expf(S[mt][nt][1]*INV_TAU) + __expf(S[mt][nt][3]*INV_TAU);
      }
    if (m0 < 896) {
      uint4* d = (uint4*)&Qs[nxt*9216 + r*72 + sg];
      d[0]=pq[0]; d[1]=pq[1]; d[2]=pq[2]; d[3]=pq[3];
    }
    __syncthreads();
  }
#pragma unroll
  for (int nt = 0; nt < 4; nt++)
#pragma unroll
    for (int j = 0; j < 2; j++) {
      float v = rs[nt][j];
      v += __shfl_xor_sync(0xffffffffu, v, 4);
      v += __shfl_xor_sync(0xffffffffu, v, 8);
      v += __shfl_xor_sync(0xffffffffu, v, 16);
      rs[nt][j] = v;
    }
  if (gi == 0) {
#pragma unroll
    for (int nt = 0; nt < 4; nt++)
#pragma unroll
      for (int j = 0; j < 2; j++)
        Zp[(wid>>2)*128 + wl_ + nt*8 + 2*tj + j] = rs[nt][j];
  }
  __syncthreads();
  if (tid < 128) {
    float zv = Zp[tid] + Zp[128 + tid];
    Z[(size_t)bh*1024 + l0 + tid] = zv;
    Zp[tid] = __frcp_rn(zv);
  }
  __syncthreads();
  // fused xdiv: Xd[b][h*64+row][l0 + 0..127] = fp16(X16 * rcpZ)
  {
    int row = tid>>2, c0_ = (tid&3)*32;
    const __half* xs = &X16[((size_t)b*1024 + h*64 + row)*1024 + l0 + c0_];
    __half* xo = &Xd[((size_t)b*1024 + h*64 + row)*1024 + l0 + c0_];
#pragma unroll
    for (int j = 0; j < 8; j++) {
      uint2 v = *(const uint2*)&xs[j*4];
      float2 f0 = __half22float2(*(__half2*)&v.x);
      float2 f1 = __half22float2(*(__half2*)&v.y);
      int c = c0_ + j*4;
      *(uint2*)&xo[j*4] = make_uint2(f2h2(f0.x*Zp[c],   f0.y*Zp[c+1]),
                                     f2h2(f1.x*Zp[c+2], f1.y*Zp[c+3]));
    }
  }
}

// ---------------------------------------------------------------------------
// opass: O[d,m] = sum_l xd[d,l] * exp(S[l,m]/tau).  3-stage cp.async ring,
// 2 syncs per l-chunk.
// smem halves: Qs@0 (9216), K_i@9216+i*4608, X_i@23040+i*4608, Ps@36864 (9216)
// ---------------------------------------------------------------------------
__global__ __launch_bounds__(256, 2) void opass_h(
    const __half* __restrict__ Xd, const __half* __restrict__ Kt,
    const __half* __restrict__ Qt, __half* __restrict__ Ot) {
  extern __shared__ __half osm[];
  __half* Qs = osm;
  unsigned* Ps2 = (unsigned*)(osm + 36864);
  const int bh = blockIdx.y, m0 = blockIdx.x*128;
  const int b = bh>>4, h = bh&15;
  const __half* Kb = Kt + (size_t)bh*65536;
  const __half* Qb = Qt + (size_t)bh*65536;
  const __half* Xg = Xd + ((size_t)b*1024 + h*64)*1024;
  const int tid = threadIdx.x, wid = tid>>5, lane = tid&31;
  const int gi = lane>>2, tj = lane&3;
  const int wm1 = (wid>>2)*64, wl1 = (wid&3)*16;
  const int wr2 = (wid>>2)*32, wn2 = (wid&3)*32;
  const unsigned smO = su32(osm);
  const int laneA = (((lane&7) + ((lane>>3)&1)*8)*72 + ((lane>>4)&1)*8)*2;
  const int laneB = (((lane&7) + ((lane>>4)&1)*8)*72 + ((lane>>3)&1)*8)*2;

  {
    int r = tid>>1, sg = (tid&1)*32;
    const uint4* s = (const uint4*)&Qb[(size_t)(m0 + r)*64 + sg];
    uint4* d = (uint4*)&Qs[r*72 + sg];
    d[0]=s[0]; d[1]=s[1]; d[2]=s[2]; d[3]=s[3];
  }

  auto issue = [&](int buf, int l0) {
#pragma unroll
    for (int i = 0; i < 2; i++) {
      int id = tid*2 + i;                 // 0..511
      int row = id>>3, c8 = (id&7)*8;
      cpa16(smO + (9216 + buf*4608 + row*72 + c8)*2,
            &Kb[(size_t)(l0 + row)*64 + c8]);
      cpa16(smO + (23040 + buf*4608 + row*72 + c8)*2,
            &Xg[(size_t)row*1024 + l0 + c8]);
    }
    CP_COMMIT();
  };
  issue(0, 0);
  issue(1, 64);

  float O[2][4][4] = {};
  for (int s = 0; s < 16; s++) {
    const int cur = s % 3;
    if (s < 15) CP_WAIT1(); else CP_WAIT0();
    __syncthreads();
    // GEMM1: S^T[m 128][l 64] = Q^T K
    float S[4][2][4] = {};
#pragma unroll
    for (int c = 0; c < 4; c++) {
      unsigned a[4][4], bb[2][2];
#pragma unroll
      for (int mt = 0; mt < 4; mt++)
        LDSM4(a[mt][0], a[mt][1], a[mt][2], a[mt][3],
              smO + ((wm1 + mt*16)*72 + c*16)*2 + laneA);
      LDSM4(bb[0][0], bb[0][1], bb[1][0], bb[1][1],
            smO + (9216 + cur*4608 + wl1*72 + c*16)*2 + laneB);
#pragma unroll
      for (int mt = 0; mt < 4; mt++)
#pragma unroll
        for (int nt = 0; nt < 2; nt++)
          mma16(S[mt][nt], a[mt][0],a[mt][1],a[mt][2],a[mt][3],
                bb[nt][0], bb[nt][1]);
    }
    // exp -> Ps[m][l]
#pragma unroll
    for (int mt = 0; mt < 4; mt++) {
      int m_ = wm1 + mt*16 + gi;
#pragma unroll
      for (int nt = 0; nt < 2; nt++) {
        int lu = wl1/2 + nt*4 + tj;
        Ps2[m_*36 + lu] =
            f2h2(__expf(S[mt][nt][0]*INV_TAU), __expf(S[mt][nt][1]*INV_TAU));
        Ps2[(m_+8)*36 + lu] =
            f2h2(__expf(S[mt][nt][2]*INV_TAU), __expf(S[mt][nt][3]*INV_TAU));
      }
    }
    __syncthreads();
    // GEMM2: O[d 64][m 128] += Xd[d][l] @ P^T
#pragma unroll
    for (int c = 0; c < 4; c++) {
      unsigned a[2][4], bb[4][2];
#pragma unroll
      for (int mt = 0; mt < 2; mt++)
        LDSM4(a[mt][0], a[mt][1], a[mt][2], a[mt][3],
              smO + (23040 + cur*4608 + (wr2 + mt*16)*72 + c*16)*2 + laneA);
      LDSM4(bb[0][0], bb[0][1], bb[1][0], bb[1][1],
            smO + (36864 + wn2*72 + c*16)*2 + laneB);
      LDSM4(bb[2][0], bb[2][1], bb[3][0], bb[3][1],
            smO + (36864 + (wn2 + 16)*72 + c*16)*2 + laneB);
#pragma unroll
      for (int mt = 0; mt < 2; mt++)
#pragma unroll
        for (int nt = 0; nt < 4; nt++)
          mma16(O[mt][nt], a[mt][0],a[mt][1],a[mt][2],a[mt][3],
                bb[nt][0], bb[nt][1]);
    }
    if (s < 14) issue((s + 2) % 3, (s + 2)*64);
  }
  // Epilogue: stage Os[m 128][d 64] over Qs, coalesced write
  __syncthreads();
  __half* Os = Qs;
#pragma unroll
  for (int mt = 0; mt < 2; mt++) {
    int d_ = wr2 + mt*16 + gi;
#pragma unroll
    for (int nt = 0; nt < 4; nt++) {
      int m_ = wn2 + nt*8 + 2*tj;
      Os[m_*72 + d_]       = __float2half(O[mt][nt][0]);
      Os[(m_+1)*72 + d_]   = __float2half(O[mt][nt][1]);
      Os[m_*72 + d_+8]     = __float2half(O[mt][nt][2]);
      Os[(m_+1)*72 + d_+8] = __float2half(O[mt][nt][3]);
    }
  }
  __syncthreads();
  {
    int m = tid>>1, sg = (tid&1)*32;
    const uint4* s = (const uint4*)&Os[m*72 + sg];
    uint4 v0 = s[0], v1 = s[1], v2 = s[2], v3 = s[3];
    __half* dst = &Ot[((size_t)b*1024 + m0 + m)*1024 + h*64 + sg];
    *(uint4*)dst        = v0;
    *(uint4*)(dst + 8)  = v1;
    *(uint4*)(dst + 16) = v2;
    *(uint4*)(dst + 24) = v3;
  }
}

// ---------------------------------------------------------------------------
extern "C" void kernel_launch(void* const* d_in, const int* in_sizes, int n_in,
                              void* d_out, int out_size) {
  (void)in_sizes; (void)n_in; (void)out_size;
  const float* x  = (const float*)d_in[0];
  const float* y  = (const float*)d_in[1];
  const float* Wk = (const float*)d_in[2];
  const float* bk = (const float*)d_in[3];
  const float* Wq = (const float*)d_in[4];
  const float* bq = (const float*)d_in[5];
  const float* Wp = (const float*)d_in[6];
  const float* bp = (const float*)d_in[7];
  float* out = (float*)d_out;

  __half *Xt, *Yt, *Otp, *X16, *Xdp, *Wh, *Ktp, *Qtp; float* Zp;
  cudaGetSymbolAddress((void**)&Xt,  g_Xt);
  cudaGetSymbolAddress((void**)&Yt,  g_Yt);
  cudaGetSymbolAddress((void**)&Otp, g_Ot);
  cudaGetSymbolAddress((void**)&X16, g_X16);
  cudaGetSymbolAddress((void**)&Xdp, g_Xd);
  cudaGetSymbolAddress((void**)&Wh,  g_Wh);
  cudaGetSymbolAddress((void**)&Ktp, g_Kt);
  cudaGetSymbolAddress((void**)&Qtp, g_Qt);
  cudaGetSymbolAddress((void**)&Zp,  g_Z);

  const int psmem = 55296*2;            // 110,592 B (3-stage ring)
  const int zsmem = 27648*2 + 1024;     // 56,320 B
  const int osmem = 46080*2;            // 92,160 B (3-stage ring)
  cudaFuncSetAttribute(proj_h,  cudaFuncAttributeMaxDynamicSharedMemorySize, psmem);
  cudaFuncSetAttribute(zpass_h, cudaFuncAttributeMaxDynamicSharedMemorySize, zsmem);
  cudaFuncSetAttribute(opass_h, cudaFuncAttributeMaxDynamicSharedMemorySize, osmem);

  dim3 tg(16, 16, 8);
  cvtW<<<3072, 256>>>(Wk, Wq, Wp, Wh);
  prep_xt<<<tg, 256>>>(x, Xt, X16);
  prep_xt<<<tg, 256>>>(y, Yt, nullptr);
  proj_h<<<dim3(8, 8, 16), 256, psmem>>>(Wh, Wh + 1024*1024, Xt, Yt,
                                         bk, bq, Ktp, Qtp, nullptr, 0);
  zpass_h<<<dim3(8, 128), 256, zsmem>>>(Ktp, Qtp, X16, Zp, Xdp);
  opass_h<<<dim3(8, 128), 256, osmem>>>(Xdp, Ktp, Qtp, Otp);
  proj_h<<<dim3(8, 8, 8), 256, psmem>>>(Wh + 2ul*1024*1024, nullptr, Otp, nullptr,
                                        bp, nullptr, nullptr, nullptr, out, 1);
}

// round 17
// speedup vs baseline: 1.0360x; 1.0360x over previous
#include <cuda_runtime.h>
#include <cuda_fp16.h>

#define INV_TAU (1.0f/512.0f)

// Scratch (no cudaMalloc allowed)
__device__ __half g_Xt[8ul*1024*1024];     // x^T fp16 [b][l][s]
__device__ __half g_Yt[8ul*1024*1024];     // y^T fp16 [b][l][s]
__device__ __half g_Ot[8ul*1024*1024];     // O^T fp16 [b][m][s]
__device__ __half g_X16[8ul*1024*1024];    // x fp16 [b][s][l]
__device__ __half g_Xd[8ul*1024*1024];     // x/Z fp16 [b][s][l]
__device__ __half g_Wh[3ul*1024*1024];     // Wk,Wq,Wp fp16 row-major
__device__ __half g_Kt[128ul*1024*64];     // K^T fp16 [bh][l][d]
__device__ __half g_Qt[128ul*1024*64];     // Q^T fp16 [bh][m][d]
__device__ float  g_Z[128ul*1024];

__device__ __forceinline__ unsigned f2h2(float a, float b) {
  __half2 h = __floats2half2_rn(a, b);
  return *(unsigned*)&h;
}
__device__ __forceinline__ unsigned su32(const void* p) {
  unsigned a;
  asm("{ .reg .u64 t; cvta.to.shared.u64 t, %1; cvt.u32.u64 %0, t; }"
      : "=r"(a) : "l"(p));
  return a;
}
__device__ __forceinline__ void mma16(float* c, unsigned a0, unsigned a1,
                                      unsigned a2, unsigned a3,
                                      unsigned b0, unsigned b1) {
  asm("mma.sync.aligned.m16n8k16.row.col.f32.f16.f16.f32 "
      "{%0,%1,%2,%3}, {%4,%5,%6,%7}, {%8,%9}, {%0,%1,%2,%3};"
      : "+f"(c[0]), "+f"(c[1]), "+f"(c[2]), "+f"(c[3])
      : "r"(a0), "r"(a1), "r"(a2), "r"(a3), "r"(b0), "r"(b1));
}
#define LDSM4(r0, r1, r2, r3, addr) \
  asm volatile("ldmatrix.sync.aligned.m8n8.x4.shared.b16 {%0,%1,%2,%3}, [%4];" \
               : "=r"(r0), "=r"(r1), "=r"(r2), "=r"(r3) : "r"(addr))
__device__ __forceinline__ void cpa16(unsigned dst, const void* src) {
  asm volatile("cp.async.ca.shared.global [%0], [%1], 16;"
               :: "r"(dst), "l"(src));
}
#define CP_COMMIT() asm volatile("cp.async.commit_group;")
#define CP_WAIT1()  asm volatile("cp.async.wait_group 1;")
#define CP_WAIT0()  asm volatile("cp.async.wait_group 0;")

// ---------------------------------------------------------------------------
// cvtW: convert the 3 weight matrices fp32->fp16 in one launch (grid 3072)
// ---------------------------------------------------------------------------
__global__ __launch_bounds__(256) void cvtW(
    const float* __restrict__ w0, const float* __restrict__ w1,
    const float* __restrict__ w2, __half* __restrict__ out) {
  int blk = blockIdx.x;
  int which = blk >> 10;
  const float* src = (which == 0) ? w0 : (which == 1) ? w1 : w2;
  size_t off = ((size_t)(blk & 1023)*256 + threadIdx.x)*4;
  float4 v = *(const float4*)&src[off];
  *(uint2*)&out[(size_t)which*1048576 + off] =
      make_uint2(f2h2(v.x, v.y), f2h2(v.z, v.w));
}

// ---------------------------------------------------------------------------
// prep_xt: read fp32 once; write fp16 transposed (Tt) and optional straight
// fp16 copy (St).
// ---------------------------------------------------------------------------
__global__ __launch_bounds__(256, 2) void prep_xt(
    const float* __restrict__ in, __half* __restrict__ Tt,
    __half* __restrict__ St) {
  __shared__ float t[64][65];
  const int z = blockIdx.z;
  const int r0 = blockIdx.y * 64, c0 = blockIdx.x * 64;
  const int tid = threadIdx.x;
  const size_t base = (size_t)z * 1024 * 1024;
  const int tr = tid >> 4, tc4 = (tid & 15) * 4;
#pragma unroll
  for (int i = 0; i < 4; i++) {
    int row = tr + i * 16;
    float4 v = *(const float4*)&in[base + (size_t)(r0 + row) * 1024 + c0 + tc4];
    t[row][tc4+0] = v.x; t[row][tc4+1] = v.y;
    t[row][tc4+2] = v.z; t[row][tc4+3] = v.w;
    if (St)
      *(uint2*)&St[base + (size_t)(r0 + row) * 1024 + c0 + tc4] =
          make_uint2(f2h2(v.x, v.y), f2h2(v.z, v.w));
  }
  __syncthreads();
#pragma unroll
  for (int i = 0; i < 4; i++) {
    int orow = tr + i * 16;
    uint2 u;
    u.x = f2h2(t[tc4+0][orow], t[tc4+1][orow]);
    u.y = f2h2(t[tc4+2][orow], t[tc4+3][orow]);
    *(uint2*)&Tt[base + (size_t)(c0 + orow) * 1024 + r0 + tc4] = u;
  }
}

// ---------------------------------------------------------------------------
// proj (R14 version): C = W fp16 @ X + bias.  k-step 64, 2-stage cp.async.
// mode 0 (grid z=16): which = z>>3 picks set; fp16 transposed per-head out.
// mode 1 (grid z=8): set 0, fp32 out.
// smem halves: A0@0 A1@9216 B0@18432 B1@27648 (stride 72), total 36864.
// ---------------------------------------------------------------------------
__global__ __launch_bounds__(256, 2) void proj_h(
    const __half* __restrict__ W0, const __half* __restrict__ W1,
    const __half* __restrict__ X0, const __half* __restrict__ X1,
    const float* __restrict__ b0f, const float* __restrict__ b1f,
    __half* __restrict__ T0, __half* __restrict__ T1,
    float* __restrict__ Cout, int mode) {
  extern __shared__ __half psm[];
  const int z = blockIdx.z;
  const int which = (mode == 0) ? (z >> 3) : 0;
  const int b = z & 7;
  const __half* Wsel = which ? W1 : W0;
  const __half* Xsel = (which ? X1 : X0) + (size_t)b*1024*1024;
  const float* bias = which ? b1f : b0f;
  const int row0 = blockIdx.y*128, col0 = blockIdx.x*128;
  const int tid = threadIdx.x, wid = tid>>5, lane = tid&31;
  const int gi = lane>>2, tj = lane&3;
  const int wm = (wid>>2)*64, wn = (wid&3)*32;
  const unsigned smA = su32(psm);
  const int laneA = (((lane&7) + ((lane>>3)&1)*8)*72 + ((lane>>4)&1)*8)*2;
  const int laneB = (((lane&7) + ((lane>>4)&1)*8)*72 + ((lane>>3)&1)*8)*2;

  float acc[4][4][4] = {};

  auto issue = [&](int buf, int k0) {
#pragma unroll
    for (int i = 0; i < 4; i++) {
      int id = tid*4 + i;                 // 0..1023
      int row = id>>3, c8 = (id&7)*8;
      cpa16(smA + (buf*9216 + row*72 + c8)*2,
            &Wsel[(size_t)(row0 + row)*1024 + k0 + c8]);
      cpa16(smA + (18432 + buf*9216 + row*72 + c8)*2,
            &Xsel[(size_t)(col0 + row)*1024 + k0 + c8]);
    }
    CP_COMMIT();
  };
  issue(0, 0);
  issue(1, 64);

  for (int s = 0; s < 16; s++) {
    const int cur = s & 1;
    if (s < 15) CP_WAIT1(); else CP_WAIT0();
    __syncthreads();
#pragma unroll
    for (int c = 0; c < 4; c++) {
      unsigned a[4][4], bb[4][2];
#pragma unroll
      for (int mt = 0; mt < 4; mt++)
        LDSM4(a[mt][0], a[mt][1], a[mt][2], a[mt][3],
              smA + (cur*9216 + (wm + mt*16)*72 + c*16)*2 + laneA);
      LDSM4(bb[0][0], bb[0][1], bb[1][0], bb[1][1],
            smA + (18432 + cur*9216 + wn*72 + c*16)*2 + laneB);
      LDSM4(bb[2][0], bb[2][1], bb[3][0], bb[3][1],
            smA + (18432 + cur*9216 + (wn + 16)*72 + c*16)*2 + laneB);
#pragma unroll
      for (int mt = 0; mt < 4; mt++)
#pragma unroll
        for (int nt = 0; nt < 4; nt++)
          mma16(acc[mt][nt], a[mt][0],a[mt][1],a[mt][2],a[mt][3],
                bb[nt][0], bb[nt][1]);
    }
    __syncthreads();
    if (s < 14) issue(cur, (s + 2)*64);
  }

  if (mode == 1) {
    float* Cb = Cout + (size_t)b*1024*1024;
#pragma unroll
    for (int mt = 0; mt < 4; mt++) {
      int r0_ = row0 + wm + mt*16 + gi;
      float bv0 = bias[r0_], bv1 = bias[r0_+8];
#pragma unroll
      for (int nt = 0; nt < 4; nt++) {
        int cc = col0 + wn + nt*8 + 2*tj;
        *(float2*)&Cb[(size_t)r0_*1024 + cc] =
            make_float2(acc[mt][nt][0]+bv0, acc[mt][nt][1]+bv0);
        *(float2*)&Cb[(size_t)(r0_+8)*1024 + cc] =
            make_float2(acc[mt][nt][2]+bv1, acc[mt][nt][3]+bv1);
      }
    }
  } else {
    __half* Tout = which ? T1 : T0;
    __half* Cts = psm;   // 128*136 halves
#pragma unroll
    for (int mt = 0; mt < 4; mt++) {
      int r_ = wm + mt*16 + gi;
      float bv0 = bias[row0 + r_], bv1 = bias[row0 + r_ + 8];
#pragma unroll
      for (int nt = 0; nt < 4; nt++) {
        int c_ = wn + nt*8 + 2*tj;
        Cts[c_*136 + r_]       = __float2half(acc[mt][nt][0] + bv0);
        Cts[(c_+1)*136 + r_]   = __float2half(acc[mt][nt][1] + bv0);
        Cts[c_*136 + r_+8]     = __float2half(acc[mt][nt][2] + bv1);
        Cts[(c_+1)*136 + r_+8] = __float2half(acc[mt][nt][3] + bv1);
      }
    }
    __syncthreads();
    int l = tid>>1, part = tid&1;
    size_t obase = ((size_t)(b*16 + (row0>>6) + part)*1024 + col0 + l)*64;
#pragma unroll
    for (int j = 0; j < 8; j++)
      *(uint4*)&Tout[obase + j*8] = *(const uint4*)&Cts[l*136 + part*64 + j*8];
  }
}

// ---------------------------------------------------------------------------
// zpass: Z[l] = sum_m exp(S[l,m]/tau), S^T = Q^T K.  Epilogue also writes
// Xd = x/Z for this (bh, l-tile) — fused xdiv.
// ---------------------------------------------------------------------------
__global__ __launch_bounds__(256, 2) void zpass_h(
    const __half* __restrict__ Kt, const __half* __restrict__ Qt,
    const __half* __restrict__ X16, float* __restrict__ Z,
    __half* __restrict__ Xd) {
  extern __shared__ __half zsm[];
  __half* Ks = zsm;
  __half* Qs = zsm + 9216;
  float* Zp = (float*)(zsm + 27648);
  const int bh = blockIdx.y, l0 = blockIdx.x*128;
  const int b = bh>>4, h = bh&15;
  const __half* Kb = Kt + (size_t)bh*65536;
  const __half* Qb = Qt + (size_t)bh*65536;
  const int tid = threadIdx.x, wid = tid>>5, lane = tid&31;
  const int gi = lane>>2, tj = lane&3;
  const int wm_ = (wid>>2)*64, wl_ = (wid&3)*32;
  const int r = tid>>1, sg = (tid&1)*32;
  const unsigned smK = su32(Ks), smQ = su32(Qs);
  const int laneA = (((lane&7) + ((lane>>3)&1)*8)*72 + ((lane>>4)&1)*8)*2;
  const int laneB = (((lane&7) + ((lane>>4)&1)*8)*72 + ((lane>>3)&1)*8)*2;

  {
    const uint4* s = (const uint4*)&Kb[(size_t)(l0 + r)*64 + sg];
    uint4* d = (uint4*)&Ks[r*72 + sg];
    d[0]=s[0]; d[1]=s[1]; d[2]=s[2]; d[3]=s[3];
  }
  uint4 pq[4];
  {
    const uint4* s = (const uint4*)&Qb[(size_t)r*64 + sg];
    pq[0]=s[0]; pq[1]=s[1]; pq[2]=s[2]; pq[3]=s[3];
    uint4* d = (uint4*)&Qs[r*72 + sg];
    d[0]=pq[0]; d[1]=pq[1]; d[2]=pq[2]; d[3]=pq[3];
  }
  __syncthreads();

  float rs[4][2] = {};
  for (int m0 = 0; m0 < 1024; m0 += 128) {
    const int cur = (m0 >> 7) & 1, nxt = cur ^ 1;
    if (m0 < 896) {
      const uint4* s = (const uint4*)&Qb[(size_t)(m0 + 128 + r)*64 + sg];
      pq[0]=s[0]; pq[1]=s[1]; pq[2]=s[2]; pq[3]=s[3];
    }
    float S[4][4][4] = {};
#pragma unroll
    for (int c = 0; c < 4; c++) {
      unsigned a[4][4], bb[4][2];
#pragma unroll
      for (int mt = 0; mt < 4; mt++)
        LDSM4(a[mt][0], a[mt][1], a[mt][2], a[mt][3],
              smQ + cur*18432 + ((wm_ + mt*16)*72 + c*16)*2 + laneA);
      LDSM4(bb[0][0], bb[0][1], bb[1][0], bb[1][1],
            smK + (wl_*72 + c*16)*2 + laneB);
      LDSM4(bb[2][0], bb[2][1], bb[3][0], bb[3][1],
            smK + ((wl_ + 16)*72 + c*16)*2 + laneB);
#pragma unroll
      for (int mt = 0; mt < 4; mt++)
#pragma unroll
        for (int nt = 0; nt < 4; nt++)
          mma16(S[mt][nt], a[mt][0],a[mt][1],a[mt][2],a[mt][3],
                bb[nt][0], bb[nt][1]);
    }
#pragma unroll
    for (int mt = 0; mt < 4; mt++)
#pragma unroll
      for (int nt = 0; nt < 4; nt++) {
        rs[nt][0] += __expf(S[mt][nt][0]*INV_TAU) + __expf(S[mt][nt][2]*INV_TAU);
        rs[nt][1] += __expf(S[mt][nt][1]*INV_TAU) + __expf(S[mt][nt][3]*INV_TAU);
      }
    if (m0 < 896) {
      uint4* d = (uint4*)&Qs[nxt*9216 + r*72 + sg];
      d[0]=pq[0]; d[1]=pq[1]; d[2]=pq[2]; d[3]=pq[3];
    }
    __syncthreads();
  }
#pragma unroll
  for (int nt = 0; nt < 4; nt++)
#pragma unroll
    for (int j = 0; j < 2; j++) {
      float v = rs[nt][j];
      v += __shfl_xor_sync(0xffffffffu, v, 4);
      v += __shfl_xor_sync(0xffffffffu, v, 8);
      v += __shfl_xor_sync(0xffffffffu, v, 16);
      rs[nt][j] = v;
    }
  if (gi == 0) {
#pragma unroll
    for (int nt = 0; nt < 4; nt++)
#pragma unroll
      for (int j = 0; j < 2; j++)
        Zp[(wid>>2)*128 + wl_ + nt*8 + 2*tj + j] = rs[nt][j];
  }
  __syncthreads();
  if (tid < 128) {
    float zv = Zp[tid] + Zp[128 + tid];
    Z[(size_t)bh*1024 + l0 + tid] = zv;
    Zp[tid] = __frcp_rn(zv);
  }
  __syncthreads();
  // fused xdiv: Xd[b][h*64+row][l0 + 0..127] = fp16(X16 * rcpZ)
  {
    int row = tid>>2, c0_ = (tid&3)*32;
    const __half* xs = &X16[((size_t)b*1024 + h*64 + row)*1024 + l0 + c0_];
    __half* xo = &Xd[((size_t)b*1024 + h*64 + row)*1024 + l0 + c0_];
#pragma unroll
    for (int j = 0; j < 8; j++) {
      uint2 v = *(const uint2*)&xs[j*4];
      float2 f0 = __half22float2(*(__half2*)&v.x);
      float2 f1 = __half22float2(*(__half2*)&v.y);
      int c = c0_ + j*4;
      *(uint2*)&xo[j*4] = make_uint2(f2h2(f0.x*Zp[c],   f0.y*Zp[c+1]),
                                     f2h2(f1.x*Zp[c+2], f1.y*Zp[c+3]));
    }
  }
}

// ---------------------------------------------------------------------------
// opass (R14 version): O[d,m] = sum_l xd[d,l] * exp(S[l,m]/tau).
// 2-stage cp.async for K and Xd; l-chunk 64; ldmatrix fragments.
// smem halves: Qs@0 (9216), K0@9216 K1@13824, X0@18432 X1@23040, Ps@27648.
// ---------------------------------------------------------------------------
__global__ __launch_bounds__(256, 2) void opass_h(
    const __half* __restrict__ Xd, const __half* __restrict__ Kt,
    const __half* __restrict__ Qt, __half* __restrict__ Ot) {
  extern __shared__ __half osm[];
  __half* Qs = osm;
  unsigned* Ps2 = (unsigned*)(osm + 27648);
  const int bh = blockIdx.y, m0 = blockIdx.x*128;
  const int b = bh>>4, h = bh&15;
  const __half* Kb = Kt + (size_t)bh*65536;
  const __half* Qb = Qt + (size_t)bh*65536;
  const __half* Xg = Xd + ((size_t)b*1024 + h*64)*1024;
  const int tid = threadIdx.x, wid = tid>>5, lane = tid&31;
  const int gi = lane>>2, tj = lane&3;
  const int wm1 = (wid>>2)*64, wl1 = (wid&3)*16;
  const int wr2 = (wid>>2)*32, wn2 = (wid&3)*32;
  const unsigned smO = su32(osm);
  const int laneA = (((lane&7) + ((lane>>3)&1)*8)*72 + ((lane>>4)&1)*8)*2;
  const int laneB = (((lane&7) + ((lane>>4)&1)*8)*72 + ((lane>>3)&1)*8)*2;

  {
    int r = tid>>1, sg = (tid&1)*32;
    const uint4* s = (const uint4*)&Qb[(size_t)(m0 + r)*64 + sg];
    uint4* d = (uint4*)&Qs[r*72 + sg];
    d[0]=s[0]; d[1]=s[1]; d[2]=s[2]; d[3]=s[3];
  }

  auto issue = [&](int buf, int l0) {
#pragma unroll
    for (int i = 0; i < 2; i++) {
      int id = tid*2 + i;                 // 0..511
      int row = id>>3, c8 = (id&7)*8;
      cpa16(smO + (9216 + buf*4608 + row*72 + c8)*2,
            &Kb[(size_t)(l0 + row)*64 + c8]);
      cpa16(smO + (18432 + buf*4608 + row*72 + c8)*2,
            &Xg[(size_t)row*1024 + l0 + c8]);
    }
    CP_COMMIT();
  };
  issue(0, 0);
  issue(1, 64);

  float O[2][4][4] = {};
  for (int s = 0; s < 16; s++) {
    const int cur = s & 1;
    if (s < 15) CP_WAIT1(); else CP_WAIT0();
    __syncthreads();
    // GEMM1: S^T[m 128][l 64] = Q^T K
    float S[4][2][4] = {};
#pragma unroll
    for (int c = 0; c < 4; c++) {
      unsigned a[4][4], bb[2][2];
#pragma unroll
      for (int mt = 0; mt < 4; mt++)
        LDSM4(a[mt][0], a[mt][1], a[mt][2], a[mt][3],
              smO + ((wm1 + mt*16)*72 + c*16)*2 + laneA);
      LDSM4(bb[0][0], bb[0][1], bb[1][0], bb[1][1],
            smO + (9216 + cur*4608 + wl1*72 + c*16)*2 + laneB);
#pragma unroll
      for (int mt = 0; mt < 4; mt++)
#pragma unroll
        for (int nt = 0; nt < 2; nt++)
          mma16(S[mt][nt], a[mt][0],a[mt][1],a[mt][2],a[mt][3],
                bb[nt][0], bb[nt][1]);
    }
    // exp -> Ps[m][l]
#pragma unroll
    for (int mt = 0; mt < 4; mt++) {
      int m_ = wm1 + mt*16 + gi;
#pragma unroll
      for (int nt = 0; nt < 2; nt++) {
        int lu = wl1/2 + nt*4 + tj;
        Ps2[m_*36 + lu] =
            f2h2(__expf(S[mt][nt][0]*INV_TAU), __expf(S[mt][nt][1]*INV_TAU));
        Ps2[(m_+8)*36 + lu] =
            f2h2(__expf(S[mt][nt][2]*INV_TAU), __expf(S[mt][nt][3]*INV_TAU));
      }
    }
    __syncthreads();
    // GEMM2: O[d 64][m 128] += Xd[d][l] @ P^T
#pragma unroll
    for (int c = 0; c < 4; c++) {
      unsigned a[2][4], bb[4][2];
#pragma unroll
      for (int mt = 0; mt < 2; mt++)
        LDSM4(a[mt][0], a[mt][1], a[mt][2], a[mt][3],
              smO + (18432 + cur*4608 + (wr2 + mt*16)*72 + c*16)*2 + laneA);
      LDSM4(bb[0][0], bb[0][1], bb[1][0], bb[1][1],
            smO + (27648 + wn2*72 + c*16)*2 + laneB);
      LDSM4(bb[2][0], bb[2][1], bb[3][0], bb[3][1],
            smO + (27648 + (wn2 + 16)*72 + c*16)*2 + laneB);
#pragma unroll
      for (int mt = 0; mt < 2; mt++)
#pragma unroll
        for (int nt = 0; nt < 4; nt++)
          mma16(O[mt][nt], a[mt][0],a[mt][1],a[mt][2],a[mt][3],
                bb[nt][0], bb[nt][1]);
    }
    __syncthreads();
    if (s < 14) issue(cur, (s + 2)*64);
  }
  // Epilogue: stage Os[m 128][d 64] over Qs, coalesced write
  __half* Os = Qs;
#pragma unroll
  for (int mt = 0; mt < 2; mt++) {
    int d_ = wr2 + mt*16 + gi;
#pragma unroll
    for (int nt = 0; nt < 4; nt++) {
      int m_ = wn2 + nt*8 + 2*tj;
      Os[m_*72 + d_]       = __float2half(O[mt][nt][0]);
      Os[(m_+1)*72 + d_]   = __float2half(O[mt][nt][1]);
      Os[m_*72 + d_+8]     = __float2half(O[mt][nt][2]);
      Os[(m_+1)*72 + d_+8] = __float2half(O[mt][nt][3]);
    }
  }
  __syncthreads();
  {
    int m = tid>>1, sg = (tid&1)*32;
    const uint4* s = (const uint4*)&Os[m*72 + sg];
    uint4 v0 = s[0], v1 = s[1], v2 = s[2], v3 = s[3];
    __half* dst = &Ot[((size_t)b*1024 + m0 + m)*1024 + h*64 + sg];
    *(uint4*)dst        = v0;
    *(uint4*)(dst + 8)  = v1;
    *(uint4*)(dst + 16) = v2;
    *(uint4*)(dst + 24) = v3;
  }
}

// ---------------------------------------------------------------------------
extern "C" void kernel_launch(void* const* d_in, const int* in_sizes, int n_in,
                              void* d_out, int out_size) {
  (void)in_sizes; (void)n_in; (void)out_size;
  const float* x  = (const float*)d_in[0];
  const float* y  = (const float*)d_in[1];
  const float* Wk = (const float*)d_in[2];
  const float* bk = (const float*)d_in[3];
  const float* Wq = (const float*)d_in[4];
  const float* bq = (const float*)d_in[5];
  const float* Wp = (const float*)d_in[6];
  const float* bp = (const float*)d_in[7];
  float* out = (float*)d_out;

  __half *Xt, *Yt, *Otp, *X16, *Xdp, *Wh, *Ktp, *Qtp; float* Zp;
  cudaGetSymbolAddress((void**)&Xt,  g_Xt);
  cudaGetSymbolAddress((void**)&Yt,  g_Yt);
  cudaGetSymbolAddress((void**)&Otp, g_Ot);
  cudaGetSymbolAddress((void**)&X16, g_X16);
  cudaGetSymbolAddress((void**)&Xdp, g_Xd);
  cudaGetSymbolAddress((void**)&Wh,  g_Wh);
  cudaGetSymbolAddress((void**)&Ktp, g_Kt);
  cudaGetSymbolAddress((void**)&Qtp, g_Qt);
  cudaGetSymbolAddress((void**)&Zp,  g_Z);

  const int psmem = 36864*2;            // 73,728 B (2-stage, R14)
  const int zsmem = 27648*2 + 1024;     // 56,320 B
  const int osmem = 36864*2;            // 73,728 B (2-stage, R14)
  cudaFuncSetAttribute(proj_h,  cudaFuncAttributeMaxDynamicSharedMemorySize, psmem);
  cudaFuncSetAttribute(zpass_h, cudaFuncAttributeMaxDynamicSharedMemorySize, zsmem);
  cudaFuncSetAttribute(opass_h, cudaFuncAttributeMaxDynamicSharedMemorySize, osmem);

  dim3 tg(16, 16, 8);
  cvtW<<<3072, 256>>>(Wk, Wq, Wp, Wh);
  prep_xt<<<tg, 256>>>(x, Xt, X16);
  prep_xt<<<tg, 256>>>(y, Yt, nullptr);
  proj_h<<<dim3(8, 8, 16), 256, psmem>>>(Wh, Wh + 1024*1024, Xt, Yt,
                                         bk, bq, Ktp, Qtp, nullptr, 0);
  zpass_h<<<dim3(8, 128), 256, zsmem>>>(Ktp, Qtp, X16, Zp, Xdp);
  opass_h<<<dim3(8, 128), 256, osmem>>>(Xdp, Ktp, Qtp, Otp);
  proj_h<<<dim3(8, 8, 8), 256, psmem>>>(Wh + 2ul*1024*1024, nullptr, Otp, nullptr,
                                        bp, nullptr, nullptr, nullptr, out, 1);
}